// round 15
// baseline (speedup 1.0000x reference)
#include <cuda_runtime.h>
#include <cuda_bf16.h>
#include <math_constants.h>
#include <cstdint>

#define N_CODES 4096
#define DIM 64
#define TILE_N 128
#define NT (N_CODES / TILE_N)
#define WARPS 4
#define BLOCK_THREADS (WARPS * 32)
#define ROWS_PER_WARP 32
#define ROWS_PER_CTA (WARPS * ROWS_PER_WARP)   // 128
#define WPAD 72                                 // padded smem row (bf16 elems) -> conflict-free LDSM
#define DELTA 4e-4f                             // sound: > 2x worst-case dropped-term err 1.6e-4

// ---------------- device scratch (no allocs allowed) ----------------
__device__ __align__(16) float g_wsq[N_CODES];
__device__ __align__(16) __nv_bfloat16 g_w1[N_CODES * DIM];
__device__ __align__(16) __nv_bfloat16 g_w2[N_CODES * DIM];
__device__ int g_nflag;
__device__ int g_flagrows[65536];

// ---------------- portable PTX wrappers ----------------
__device__ __forceinline__ void mma_16816(float c[4], const uint32_t a[4],
                                          uint32_t b0, uint32_t b1) {
    asm volatile(
        "mma.sync.aligned.m16n8k16.row.col.f32.bf16.bf16.f32 "
        "{%0,%1,%2,%3}, {%4,%5,%6,%7}, {%8,%9}, {%0,%1,%2,%3};"
        : "+f"(c[0]), "+f"(c[1]), "+f"(c[2]), "+f"(c[3])
        : "r"(a[0]), "r"(a[1]), "r"(a[2]), "r"(a[3]), "r"(b0), "r"(b1));
}
__device__ __forceinline__ void ldsm_x2(uint32_t& r0, uint32_t& r1, uint32_t saddr) {
    asm volatile("ldmatrix.sync.aligned.m8n8.x2.shared.b16 {%0,%1}, [%2];"
                 : "=r"(r0), "=r"(r1) : "r"(saddr));
}
__device__ __forceinline__ uint32_t pack_bf16x2(float lo, float hi) {
    __nv_bfloat162 t = __floats2bfloat162_rn(lo, hi);
    return *reinterpret_cast<uint32_t*>(&t);
}

// ---------------- kernel 1: prep (warp-per-row, coalesced bf16 split) ----------------
__global__ void prep_kernel(const float* __restrict__ w) {
    const int gtid = blockIdx.x * blockDim.x + threadIdx.x;
    const int row = gtid >> 5, lane = gtid & 31;
    if (gtid == 0) g_nflag = 0;
    if (row >= N_CODES) return;
    float2 v = *(const float2*)(w + (size_t)row * DIM + lane * 2);
    float s = v.x * v.x + v.y * v.y;
#pragma unroll
    for (int off = 16; off; off >>= 1) s += __shfl_xor_sync(0xffffffffu, s, off);
    __nv_bfloat162 h1 = __floats2bfloat162_rn(v.x, v.y);
    float rx = v.x - __bfloat162float(h1.x);
    float ry = v.y - __bfloat162float(h1.y);
    __nv_bfloat162 h2 = __floats2bfloat162_rn(rx, ry);
    *(__nv_bfloat162*)(g_w1 + (size_t)row * DIM + lane * 2) = h1;
    *(__nv_bfloat162*)(g_w2 + (size_t)row * DIM + lane * 2) = h2;
    if (lane == 0) g_wsq[row] = s;
}

// ---------------- kernel 2: fused bf16x2 mma.sync GEMM + argmin ----------------
__global__ __launch_bounds__(BLOCK_THREADS)
void vq_main(const float* __restrict__ x, const float* __restrict__ w,
             float* __restrict__ out, float* __restrict__ out_idx) {
    __shared__ __nv_bfloat16 ws1[TILE_N * WPAD];
    __shared__ __nv_bfloat16 ws2[TILE_N * WPAD];
    __shared__ float s_wsq[TILE_N];
    __shared__ int s_bj[WARPS][ROWS_PER_WARP];
    __shared__ unsigned char s_fl[WARPS][ROWS_PER_WARP];

    const int tid = threadIdx.x, lane = tid & 31, wid = tid >> 5;
    const int ctarow = blockIdx.x * ROWS_PER_CTA;
    const int wrow = ctarow + wid * ROWS_PER_WARP;

    // ---- A fragments: 2 row-sets x 4 k-chunks x 4 regs, hi + lo splits ----
    uint32_t A1[2][4][4], A2[2][4][4];
#pragma unroll
    for (int s = 0; s < 2; s++)
#pragma unroll
        for (int kc = 0; kc < 4; kc++)
#pragma unroll
            for (int f = 0; f < 4; f++) {
                int r = wrow + s * 16 + (lane >> 2) + (f & 1) * 8;
                int c = kc * 16 + (lane & 3) * 2 + (f >> 1) * 8;
                float2 v = *(const float2*)(x + (size_t)r * DIM + c);
                __nv_bfloat162 h1 = __floats2bfloat162_rn(v.x, v.y);
                float rx = v.x - __bfloat162float(h1.x);
                float ry = v.y - __bfloat162float(h1.y);
                A1[s][kc][f] = *reinterpret_cast<uint32_t*>(&h1);
                A2[s][kc][f] = pack_bf16x2(rx, ry);
            }

    // per-thread rows: 0: wrow+lane/4, 1: +8, 2: +16, 3: +24
    float bv[4] = {CUDART_INF_F, CUDART_INF_F, CUDART_INF_F, CUDART_INF_F};
    float b2v[4] = {CUDART_INF_F, CUDART_INF_F, CUDART_INF_F, CUDART_INF_F};
    int bj[4] = {0, 0, 0, 0};

    const int l16 = lane & 15;
    const uint32_t sb1 = (uint32_t)__cvta_generic_to_shared(ws1);
    const uint32_t sb2 = (uint32_t)__cvta_generic_to_shared(ws2);
    const uint32_t ldsm_toff = (uint32_t)((l16 & 7) * (WPAD * 2) + (l16 >> 3) * 16);

    for (int t = 0; t < NT; t++) {
        __syncthreads();
        // load 128-code tile of both splits into padded smem (8 uint4 per thread per split)
        const uint4* gw1 = (const uint4*)(g_w1 + (size_t)t * TILE_N * DIM);
        const uint4* gw2 = (const uint4*)(g_w2 + (size_t)t * TILE_N * DIM);
#pragma unroll
        for (int i = 0; i < 8; i++) {
            int g = tid + i * BLOCK_THREADS;       // 0..1023 (uint4 units)
            int c = g >> 3, q = g & 7;
            *(uint4*)((char*)ws1 + c * (WPAD * 2) + q * 16) = gw1[g];
            *(uint4*)((char*)ws2 + c * (WPAD * 2) + q * 16) = gw2[g];
        }
        if (tid < TILE_N) s_wsq[tid] = g_wsq[t * TILE_N + tid];
        __syncthreads();

        for (int nb = 0; nb < TILE_N / 8; nb++) {
            // 4 chains, 3 product terms: ac[s][0] <- x1w1 + x2w1 ; ac[s][1] <- x1w2
            // (x2.w2 dropped: worst-case 1.6e-4 < DELTA/2)
            float ac[2][2][4];
#pragma unroll
            for (int s = 0; s < 2; s++)
#pragma unroll
                for (int p = 0; p < 2; p++)
#pragma unroll
                    for (int e = 0; e < 4; e++) ac[s][p][e] = 0.f;

            uint32_t nboff = (uint32_t)(nb * 8 * (WPAD * 2)) + ldsm_toff;
#pragma unroll
            for (int kc = 0; kc < 4; kc++) {
                uint32_t b1a, b1b, b2a, b2b;
                uint32_t koff = nboff + kc * 32;
                ldsm_x2(b1a, b1b, sb1 + koff);
                ldsm_x2(b2a, b2b, sb2 + koff);
#pragma unroll
                for (int s = 0; s < 2; s++) {
                    mma_16816(ac[s][0], A1[s][kc], b1a, b1b);   // x1.w1
                    mma_16816(ac[s][1], A1[s][kc], b2a, b2b);   // x1.w2
                    mma_16816(ac[s][0], A2[s][kc], b1a, b1b);   // x2.w1
                }
            }

            // epilogue: scores = wsq - 2*dot
            int nloc = nb * 8 + (lane & 3) * 2;
            int n0 = t * TILE_N + nloc;
            float2 wq = *(const float2*)&s_wsq[nloc];
#pragma unroll
            for (int s = 0; s < 2; s++) {
                float d0 = ac[s][0][0] + ac[s][1][0];
                float d1 = ac[s][0][1] + ac[s][1][1];
                float d2 = ac[s][0][2] + ac[s][1][2];
                float d3 = ac[s][0][3] + ac[s][1][3];
                float s0 = fmaf(-2.f, d0, wq.x);
                float s1 = fmaf(-2.f, d1, wq.y);
                float s2 = fmaf(-2.f, d2, wq.x);
                float s3 = fmaf(-2.f, d3, wq.y);
                int r0 = 2 * s, r1 = 2 * s + 1;
                if (s0 < bv[r0]) { b2v[r0] = bv[r0]; bv[r0] = s0; bj[r0] = n0; }
                else             { b2v[r0] = fminf(b2v[r0], s0); }
                if (s1 < bv[r0]) { b2v[r0] = bv[r0]; bv[r0] = s1; bj[r0] = n0 + 1; }
                else             { b2v[r0] = fminf(b2v[r0], s1); }
                if (s2 < bv[r1]) { b2v[r1] = bv[r1]; bv[r1] = s2; bj[r1] = n0; }
                else             { b2v[r1] = fminf(b2v[r1], s2); }
                if (s3 < bv[r1]) { b2v[r1] = bv[r1]; bv[r1] = s3; bj[r1] = n0 + 1; }
                else             { b2v[r1] = fminf(b2v[r1], s3); }
            }
        }
    }

    // ---- quad reduce (threads sharing same rows differ only in lane&3) ----
#pragma unroll
    for (int off = 1; off <= 2; off <<= 1) {
#pragma unroll
        for (int i = 0; i < 4; i++) {
            float ob  = __shfl_xor_sync(0xffffffffu, bv[i], off);
            float ob2 = __shfl_xor_sync(0xffffffffu, b2v[i], off);
            int   oj  = __shfl_xor_sync(0xffffffffu, bj[i], off);
            float nb2 = fminf(fmaxf(bv[i], ob), fminf(b2v[i], ob2));
            if (ob < bv[i]) { bv[i] = ob; bj[i] = oj; }
            b2v[i] = nb2;
        }
    }
    if ((lane & 3) == 0) {
#pragma unroll
        for (int i = 0; i < 4; i++) {
            int lr = (lane >> 2) + i * 8;
            s_bj[wid][lr] = bj[i];
            s_fl[wid][lr] = (b2v[i] - bv[i] < DELTA) ? 1 : 0;
        }
    }
    __syncwarp();

    // ---- per-row output: gather codeword, idx, flag ----
    {
        const int grow = wrow + lane;
        const int jv = s_bj[wid][lane];
        const float4* wr = (const float4*)(w + (size_t)jv * DIM);
        float4* orow = (float4*)(out + (size_t)grow * DIM);
#pragma unroll
        for (int k = 0; k < DIM / 4; k++) orow[k] = wr[k];
        if (out_idx) out_idx[grow] = (float)jv;
        if (s_fl[wid][lane]) {
            int slot = atomicAdd(&g_nflag, 1);
            g_flagrows[slot] = grow;
        }
    }
}

// ---------------- kernel 3: exact fp32 rescore of flagged rows (warp per row) ----------------
__global__ void cleanup_kernel(const float* __restrict__ x, const float* __restrict__ w,
                               float* __restrict__ out, float* __restrict__ out_idx) {
    const int nf = g_nflag;
    const int lane = threadIdx.x & 31;
    const int gwarp = (blockIdx.x * blockDim.x + threadIdx.x) >> 5;
    const int nwarps = (gridDim.x * blockDim.x) >> 5;

    for (int i = gwarp; i < nf; i += nwarps) {
        const int row = g_flagrows[i];
        float4 xr[DIM / 4];
        const float4* xp = (const float4*)(x + (size_t)row * DIM);
#pragma unroll
        for (int k = 0; k < DIM / 4; k++) xr[k] = xp[k];

        float best = CUDART_INF_F;
        int bj = 0x7fffffff;
        for (int j = lane; j < N_CODES; j += 32) {
            const float4* wp = (const float4*)(w + (size_t)j * DIM);
            float d0 = 0.f, d1 = 0.f, d2 = 0.f, d3 = 0.f;
#pragma unroll
            for (int k = 0; k < DIM / 4; k++) {
                float4 wv = wp[k];
                d0 = fmaf(xr[k].x, wv.x, d0);
                d1 = fmaf(xr[k].y, wv.y, d1);
                d2 = fmaf(xr[k].z, wv.z, d2);
                d3 = fmaf(xr[k].w, wv.w, d3);
            }
            float s = fmaf(-2.0f, (d0 + d1) + (d2 + d3), g_wsq[j]);
            if (s < best) { best = s; bj = j; }
        }
#pragma unroll
        for (int off = 16; off; off >>= 1) {
            float ob = __shfl_down_sync(0xffffffffu, best, off);
            int   oj = __shfl_down_sync(0xffffffffu, bj, off);
            if (ob < best || (ob == best && oj < bj)) { best = ob; bj = oj; }
        }
        bj = __shfl_sync(0xffffffffu, bj, 0);

        const float2* wr = (const float2*)(w + (size_t)bj * DIM);
        float2* orow = (float2*)(out + (size_t)row * DIM);
        orow[lane] = wr[lane];
        if (lane == 0 && out_idx) out_idx[row] = (float)bj;
    }
}

// ---------------- launch ----------------
extern "C" void kernel_launch(void* const* d_in, const int* in_sizes, int n_in,
                              void* d_out, int out_size) {
    const float* x = (const float*)d_in[0];
    const float* w = (const float*)d_in[1];
    float* out = (float*)d_out;

    const int n_rows = in_sizes[0] / DIM;   // 65536

    float* out_idx = nullptr;
    if ((size_t)out_size >= (size_t)n_rows * DIM + (size_t)n_rows)
        out_idx = out + (size_t)n_rows * DIM;

    prep_kernel<<<(N_CODES * 32) / 256, 256>>>(w);
    vq_main<<<n_rows / ROWS_PER_CTA, BLOCK_THREADS>>>(x, w, out, out_idx);
    cleanup_kernel<<<128, 128>>>(x, w, out, out_idx);
}

// round 17
// speedup vs baseline: 1.2778x; 1.2778x over previous
#include <cuda_runtime.h>
#include <cuda_bf16.h>
#include <math_constants.h>
#include <cstdint>

#define N_CODES 4096
#define DIM 64
#define TILE_N 128
#define NT (N_CODES / TILE_N)
#define WARPS 4
#define BLOCK_THREADS (WARPS * 32)
#define ROWS_PER_WARP 32
#define ROWS_PER_CTA (WARPS * ROWS_PER_WARP)   // 128
#define WPAD 72                                 // padded smem row (bf16 elems) -> conflict-free LDSM
#define ROWB (WPAD * 2)                         // 144 bytes
#define DELTA 1e-4f                             // bf16 4-term score err ~1e-6 -> 100x margin

// ---------------- device scratch (no allocs allowed) ----------------
__device__ __align__(16) float g_wsq[N_CODES];
__device__ __align__(16) __nv_bfloat16 g_w1[N_CODES * DIM];
__device__ __align__(16) __nv_bfloat16 g_w2[N_CODES * DIM];
__device__ int g_nflag;
__device__ int g_flagrows[65536];

// ---------------- portable PTX wrappers ----------------
__device__ __forceinline__ void mma_16816(float c[4], const uint32_t a[4],
                                          uint32_t b0, uint32_t b1) {
    asm volatile(
        "mma.sync.aligned.m16n8k16.row.col.f32.bf16.bf16.f32 "
        "{%0,%1,%2,%3}, {%4,%5,%6,%7}, {%8,%9}, {%0,%1,%2,%3};"
        : "+f"(c[0]), "+f"(c[1]), "+f"(c[2]), "+f"(c[3])
        : "r"(a[0]), "r"(a[1]), "r"(a[2]), "r"(a[3]), "r"(b0), "r"(b1));
}
// x4: all 32 lanes supply addresses; lane l -> matrix l>>3, row l&7
__device__ __forceinline__ void ldsm_x4(uint32_t r[4], uint32_t saddr) {
    asm volatile("ldmatrix.sync.aligned.m8n8.x4.shared.b16 {%0,%1,%2,%3}, [%4];"
                 : "=r"(r[0]), "=r"(r[1]), "=r"(r[2]), "=r"(r[3]) : "r"(saddr));
}
__device__ __forceinline__ uint32_t pack_bf16x2(float lo, float hi) {
    __nv_bfloat162 t = __floats2bfloat162_rn(lo, hi);
    return *reinterpret_cast<uint32_t*>(&t);
}

// ---------------- kernel 1: prep (warp-per-row, coalesced bf16 split) ----------------
__global__ void prep_kernel(const float* __restrict__ w) {
    const int gtid = blockIdx.x * blockDim.x + threadIdx.x;
    const int row = gtid >> 5, lane = gtid & 31;
    if (gtid == 0) g_nflag = 0;
    if (row >= N_CODES) return;
    float2 v = *(const float2*)(w + (size_t)row * DIM + lane * 2);
    float s = v.x * v.x + v.y * v.y;
#pragma unroll
    for (int off = 16; off; off >>= 1) s += __shfl_xor_sync(0xffffffffu, s, off);
    __nv_bfloat162 h1 = __floats2bfloat162_rn(v.x, v.y);
    float rx = v.x - __bfloat162float(h1.x);
    float ry = v.y - __bfloat162float(h1.y);
    __nv_bfloat162 h2 = __floats2bfloat162_rn(rx, ry);
    *(__nv_bfloat162*)(g_w1 + (size_t)row * DIM + lane * 2) = h1;
    *(__nv_bfloat162*)(g_w2 + (size_t)row * DIM + lane * 2) = h2;
    if (lane == 0) g_wsq[row] = s;
}

// ---------------- kernel 2: fused bf16x2 mma.sync GEMM + argmin ----------------
__global__ __launch_bounds__(BLOCK_THREADS)
void vq_main(const float* __restrict__ x, const float* __restrict__ w,
             float* __restrict__ out, float* __restrict__ out_idx) {
    __shared__ __nv_bfloat16 ws1[TILE_N * WPAD];
    __shared__ __nv_bfloat16 ws2[TILE_N * WPAD];
    __shared__ float s_wsq[TILE_N];
    __shared__ int s_bj[WARPS][ROWS_PER_WARP];
    __shared__ unsigned char s_fl[WARPS][ROWS_PER_WARP];

    const int tid = threadIdx.x, lane = tid & 31, wid = tid >> 5;
    const int ctarow = blockIdx.x * ROWS_PER_CTA;
    const int wrow = ctarow + wid * ROWS_PER_WARP;

    // ---- A fragments: 2 row-sets x 4 k-chunks x 4 regs, hi + lo splits ----
    uint32_t A1[2][4][4], A2[2][4][4];
#pragma unroll
    for (int s = 0; s < 2; s++)
#pragma unroll
        for (int kc = 0; kc < 4; kc++)
#pragma unroll
            for (int f = 0; f < 4; f++) {
                int r = wrow + s * 16 + (lane >> 2) + (f & 1) * 8;
                int c = kc * 16 + (lane & 3) * 2 + (f >> 1) * 8;
                float2 v = *(const float2*)(x + (size_t)r * DIM + c);
                __nv_bfloat162 h1 = __floats2bfloat162_rn(v.x, v.y);
                float rx = v.x - __bfloat162float(h1.x);
                float ry = v.y - __bfloat162float(h1.y);
                A1[s][kc][f] = *reinterpret_cast<uint32_t*>(&h1);
                A2[s][kc][f] = pack_bf16x2(rx, ry);
            }

    // per-thread rows: 0: wrow+lane/4, 1: +8, 2: +16, 3: +24
    float bv[4] = {CUDART_INF_F, CUDART_INF_F, CUDART_INF_F, CUDART_INF_F};
    float b2v[4] = {CUDART_INF_F, CUDART_INF_F, CUDART_INF_F, CUDART_INF_F};
    int bj[4] = {0, 0, 0, 0};

    const uint32_t sb1 = (uint32_t)__cvta_generic_to_shared(ws1);
    const uint32_t sb2 = (uint32_t)__cvta_generic_to_shared(ws2);
    // x4 per-lane base: row = lane&7, chunk-group = lane>>3 (chunks 0-3 or 4-7 via +64)
    const uint32_t ldsm4_toff = (uint32_t)((lane & 7) * ROWB + (lane >> 3) * 16);

    // B register double-buffer: [buf][split][kc-pair][4 regs]
    uint32_t B1[2][2][4], B2[2][2][4];

    for (int t = 0; t < NT; t++) {
        __syncthreads();
        // load 128-code tile of both splits into padded smem (8 uint4 per thread per split)
        const uint4* gw1 = (const uint4*)(g_w1 + (size_t)t * TILE_N * DIM);
        const uint4* gw2 = (const uint4*)(g_w2 + (size_t)t * TILE_N * DIM);
#pragma unroll
        for (int i = 0; i < 8; i++) {
            int g = tid + i * BLOCK_THREADS;       // 0..1023 (uint4 units)
            int c = g >> 3, q = g & 7;
            *(uint4*)((char*)ws1 + c * ROWB + q * 16) = gw1[g];
            *(uint4*)((char*)ws2 + c * ROWB + q * 16) = gw2[g];
        }
        if (tid < TILE_N) s_wsq[tid] = g_wsq[t * TILE_N + tid];
        __syncthreads();

        // prime buffer 0 with nb=0
        {
            uint32_t base = ldsm4_toff;            // nb = 0
            ldsm_x4(B1[0][0], sb1 + base);
            ldsm_x4(B1[0][1], sb1 + base + 64);
            ldsm_x4(B2[0][0], sb2 + base);
            ldsm_x4(B2[0][1], sb2 + base + 64);
        }

#pragma unroll
        for (int nbp = 0; nbp < 8; nbp++) {
#pragma unroll
            for (int h = 0; h < 2; h++) {          // h selects buffer (static after unroll)
                const int nb = 2 * nbp + h;
                // prefetch nb+1 into the other buffer (hidden under the 32 MMAs below)
                if (nb < 15) {
                    uint32_t base = (uint32_t)((nb + 1) * 8 * ROWB) + ldsm4_toff;
                    ldsm_x4(B1[h ^ 1][0], sb1 + base);
                    ldsm_x4(B1[h ^ 1][1], sb1 + base + 64);
                    ldsm_x4(B2[h ^ 1][0], sb2 + base);
                    ldsm_x4(B2[h ^ 1][1], sb2 + base + 64);
                }

                // 4 chains as R10: [rowset][bsplit]; all 4 product terms kept
                float ac[2][2][4];
#pragma unroll
                for (int s = 0; s < 2; s++)
#pragma unroll
                    for (int p = 0; p < 2; p++)
#pragma unroll
                        for (int e = 0; e < 4; e++) ac[s][p][e] = 0.f;

#pragma unroll
                for (int kc = 0; kc < 4; kc++) {
                    const uint32_t b1a = B1[h][kc >> 1][(kc & 1) * 2];
                    const uint32_t b1b = B1[h][kc >> 1][(kc & 1) * 2 + 1];
                    const uint32_t b2a = B2[h][kc >> 1][(kc & 1) * 2];
                    const uint32_t b2b = B2[h][kc >> 1][(kc & 1) * 2 + 1];
#pragma unroll
                    for (int s = 0; s < 2; s++) {
                        mma_16816(ac[s][0], A1[s][kc], b1a, b1b);   // x1.w1
                        mma_16816(ac[s][1], A1[s][kc], b2a, b2b);   // x1.w2
                        mma_16816(ac[s][0], A2[s][kc], b1a, b1b);   // x2.w1
                        mma_16816(ac[s][1], A2[s][kc], b2a, b2b);   // x2.w2
                    }
                }

                // epilogue: scores = wsq - 2*dot
                int nloc = nb * 8 + (lane & 3) * 2;
                int n0 = t * TILE_N + nloc;
                float2 wq = *(const float2*)&s_wsq[nloc];
#pragma unroll
                for (int s = 0; s < 2; s++) {
                    float d0 = ac[s][0][0] + ac[s][1][0];
                    float d1 = ac[s][0][1] + ac[s][1][1];
                    float d2 = ac[s][0][2] + ac[s][1][2];
                    float d3 = ac[s][0][3] + ac[s][1][3];
                    float s0 = fmaf(-2.f, d0, wq.x);
                    float s1 = fmaf(-2.f, d1, wq.y);
                    float s2 = fmaf(-2.f, d2, wq.x);
                    float s3 = fmaf(-2.f, d3, wq.y);
                    int r0 = 2 * s, r1 = 2 * s + 1;
                    if (s0 < bv[r0]) { b2v[r0] = bv[r0]; bv[r0] = s0; bj[r0] = n0; }
                    else             { b2v[r0] = fminf(b2v[r0], s0); }
                    if (s1 < bv[r0]) { b2v[r0] = bv[r0]; bv[r0] = s1; bj[r0] = n0 + 1; }
                    else             { b2v[r0] = fminf(b2v[r0], s1); }
                    if (s2 < bv[r1]) { b2v[r1] = bv[r1]; bv[r1] = s2; bj[r1] = n0; }
                    else             { b2v[r1] = fminf(b2v[r1], s2); }
                    if (s3 < bv[r1]) { b2v[r1] = bv[r1]; bv[r1] = s3; bj[r1] = n0 + 1; }
                    else             { b2v[r1] = fminf(b2v[r1], s3); }
                }
            }
        }
    }

    // ---- quad reduce (threads sharing same rows differ only in lane&3) ----
#pragma unroll
    for (int off = 1; off <= 2; off <<= 1) {
#pragma unroll
        for (int i = 0; i < 4; i++) {
            float ob  = __shfl_xor_sync(0xffffffffu, bv[i], off);
            float ob2 = __shfl_xor_sync(0xffffffffu, b2v[i], off);
            int   oj  = __shfl_xor_sync(0xffffffffu, bj[i], off);
            float nb2 = fminf(fmaxf(bv[i], ob), fminf(b2v[i], ob2));
            if (ob < bv[i]) { bv[i] = ob; bj[i] = oj; }
            b2v[i] = nb2;
        }
    }
    if ((lane & 3) == 0) {
#pragma unroll
        for (int i = 0; i < 4; i++) {
            int lr = (lane >> 2) + i * 8;
            s_bj[wid][lr] = bj[i];
            s_fl[wid][lr] = (b2v[i] - bv[i] < DELTA) ? 1 : 0;
        }
    }
    __syncwarp();

    // ---- per-row output: gather codeword, idx, flag ----
    {
        const int grow = wrow + lane;
        const int jv = s_bj[wid][lane];
        const float4* wr = (const float4*)(w + (size_t)jv * DIM);
        float4* orow = (float4*)(out + (size_t)grow * DIM);
#pragma unroll
        for (int k = 0; k < DIM / 4; k++) orow[k] = wr[k];
        if (out_idx) out_idx[grow] = (float)jv;
        if (s_fl[wid][lane]) {
            int slot = atomicAdd(&g_nflag, 1);
            g_flagrows[slot] = grow;
        }
    }
}

// ---------------- kernel 3: exact fp32 rescore of flagged rows (warp per row) ----------------
__global__ void cleanup_kernel(const float* __restrict__ x, const float* __restrict__ w,
                               float* __restrict__ out, float* __restrict__ out_idx) {
    const int nf = g_nflag;
    const int lane = threadIdx.x & 31;
    const int gwarp = (blockIdx.x * blockDim.x + threadIdx.x) >> 5;
    const int nwarps = (gridDim.x * blockDim.x) >> 5;

    for (int i = gwarp; i < nf; i += nwarps) {
        const int row = g_flagrows[i];
        float4 xr[DIM / 4];
        const float4* xp = (const float4*)(x + (size_t)row * DIM);
#pragma unroll
        for (int k = 0; k < DIM / 4; k++) xr[k] = xp[k];

        float best = CUDART_INF_F;
        int bj = 0x7fffffff;
        for (int j = lane; j < N_CODES; j += 32) {
            const float4* wp = (const float4*)(w + (size_t)j * DIM);
            float d0 = 0.f, d1 = 0.f, d2 = 0.f, d3 = 0.f;
#pragma unroll
            for (int k = 0; k < DIM / 4; k++) {
                float4 wv = wp[k];
                d0 = fmaf(xr[k].x, wv.x, d0);
                d1 = fmaf(xr[k].y, wv.y, d1);
                d2 = fmaf(xr[k].z, wv.z, d2);
                d3 = fmaf(xr[k].w, wv.w, d3);
            }
            float s = fmaf(-2.0f, (d0 + d1) + (d2 + d3), g_wsq[j]);
            if (s < best) { best = s; bj = j; }
        }
#pragma unroll
        for (int off = 16; off; off >>= 1) {
            float ob = __shfl_down_sync(0xffffffffu, best, off);
            int   oj = __shfl_down_sync(0xffffffffu, bj, off);
            if (ob < best || (ob == best && oj < bj)) { best = ob; bj = oj; }
        }
        bj = __shfl_sync(0xffffffffu, bj, 0);

        const float2* wr = (const float2*)(w + (size_t)bj * DIM);
        float2* orow = (float2*)(out + (size_t)row * DIM);
        orow[lane] = wr[lane];
        if (lane == 0 && out_idx) out_idx[row] = (float)bj;
    }
}

// ---------------- launch ----------------
extern "C" void kernel_launch(void* const* d_in, const int* in_sizes, int n_in,
                              void* d_out, int out_size) {
    const float* x = (const float*)d_in[0];
    const float* w = (const float*)d_in[1];
    float* out = (float*)d_out;

    const int n_rows = in_sizes[0] / DIM;   // 65536

    float* out_idx = nullptr;
    if ((size_t)out_size >= (size_t)n_rows * DIM + (size_t)n_rows)
        out_idx = out + (size_t)n_rows * DIM;

    prep_kernel<<<(N_CODES * 32) / 256, 256>>>(w);
    vq_main<<<n_rows / ROWS_PER_CTA, BLOCK_THREADS>>>(x, w, out, out_idx);
    cleanup_kernel<<<128, 128>>>(x, w, out, out_idx);
}